// round 15
// baseline (speedup 1.0000x reference)
#include <cuda_runtime.h>
#include <cuda_fp16.h>
#include <cstdint>

#define ZD            16
#define KN            64
#define NTHREADS      256
#define WARPS         8
#define TPW           8                        // iterations per warp (32 rows each)
#define ROWS_PER_WARP (TPW * 32)               // 256
#define ROWS_PER_CTA  (WARPS * ROWS_PER_WARP)  // 2048

#define STAGES        3
#define STAGE_BYTES   2048                     // 32 rows x 64 B per warp
#define SMEM_DYN      (STAGES * WARPS * STAGE_BYTES)   // 48 KB

// ---- helpers ---------------------------------------------------------------
__device__ __forceinline__ uint32_t pack_h2(float lo, float hi) {
    uint32_t r;
    asm("cvt.rn.f16x2.f32 %0, %1, %2;" : "=r"(r) : "f"(hi), "f"(lo));
    return r;
}
__device__ __forceinline__ uint32_t tanh2(uint32_t h2) {
    uint32_t r;
    asm("tanh.approx.f16x2 %0, %1;" : "=r"(r) : "r"(h2));
    return r;
}
__device__ __forceinline__ float tanh_a(float x) {
    float r;
    asm("tanh.approx.f32 %0, %1;" : "=f"(r) : "f"(x));
    return r;
}
__device__ __forceinline__ uint32_t smem_u32(const void* p) {
    uint32_t a;
    asm("{ .reg .u64 t; cvta.to.shared.u64 t, %1; cvt.u32.u64 %0, t; }" : "=r"(a) : "l"(p));
    return a;
}
__device__ __forceinline__ void cp_async16(uint32_t dst, const void* src) {
    asm volatile("cp.async.cg.shared.global [%0], [%1], 16;" :: "r"(dst), "l"(src));
}
#define CP_COMMIT() asm volatile("cp.async.commit_group;" ::: "memory")
#define CP_WAIT2()  asm volatile("cp.async.wait_group 2;" ::: "memory")

__device__ __forceinline__ float2 lds64(uint32_t addr) {
    float2 v;
    asm volatile("ld.shared.v2.f32 {%0, %1}, [%2];" : "=f"(v.x), "=f"(v.y) : "r"(addr));
    return v;
}
// fp16 MMA, fp32 accum, C preloaded with {c0, c1, c0, c1}
__device__ __forceinline__ void mma_h_init(float* d, const uint32_t* a,
                                           uint32_t b0, uint32_t b1,
                                           float c0, float c1) {
    asm("mma.sync.aligned.m16n8k16.row.col.f32.f16.f16.f32 "
        "{%0,%1,%2,%3}, {%4,%5,%6,%7}, {%8,%9}, {%10,%11,%12,%13};"
        : "=f"(d[0]), "=f"(d[1]), "=f"(d[2]), "=f"(d[3])
        : "r"(a[0]), "r"(a[1]), "r"(a[2]), "r"(a[3]),
          "r"(b0), "r"(b1),
          "f"(c0), "f"(c1), "f"(c0), "f"(c1));
}
// fp16 MMA, fp32 accum in-place (C = D)
__device__ __forceinline__ void mma_h_acc(float* d, const uint32_t* a,
                                          uint32_t b0, uint32_t b1) {
    asm("mma.sync.aligned.m16n8k16.row.col.f32.f16.f16.f32 "
        "{%0,%1,%2,%3}, {%4,%5,%6,%7}, {%8,%9}, {%0,%1,%2,%3};"
        : "+f"(d[0]), "+f"(d[1]), "+f"(d[2]), "+f"(d[3])
        : "r"(a[0]), "r"(a[1]), "r"(a[2]), "r"(a[3]),
          "r"(b0), "r"(b1));
}

// ---- main kernel -----------------------------------------------------------
__global__ void __launch_bounds__(NTHREADS) mave_mma(
    const float* __restrict__ z, const float* __restrict__ a0p,
    const float* __restrict__ bkp, const float* __restrict__ ck,
    const float* __restrict__ dkp, float* __restrict__ out)
{
    extern __shared__ char zstage[];          // [STAGES][WARPS][2048]
    __shared__ float2 sdk[KN / 2];            // {dk0, dk1} per column pair

    const int tid  = threadIdx.x;
    const int wid  = tid >> 5;
    const int lane = tid & 31;
    const int quad = lane >> 2;     // 0..7
    const int qid  = lane & 3;      // 0..3

    if (tid < KN / 2) {
        float2 v; v.x = dkp[2 * tid]; v.y = dkp[2 * tid + 1];
        sdk[tid] = v;
    }
    __syncthreads();
    const float a0 = a0p[0];

    // constant B fragments for MMA1: ck as plain fp16, 8 n-tiles, 16 regs
    uint32_t bh[8][2];
    #pragma unroll
    for (int j = 0; j < 8; ++j) {
        const float* cr = ck + (j * 8 + quad) * ZD + qid * 2;
        float2 g0 = *reinterpret_cast<const float2*>(cr);
        float2 g1 = *reinterpret_cast<const float2*>(cr + 8);
        bh[j][0] = pack_h2(g0.x, g0.y);
        bh[j][1] = pack_h2(g1.x, g1.y);
    }
    // B fragments for MMA2 (bk over the 64-node K dim, broadcast across N):
    // group g covers nodes [g*16, g*16+16): b0 = k 2qid(+1), b1 = k 2qid+8(+9)
    uint32_t bkf[4][2];
    #pragma unroll
    for (int g = 0; g < 4; ++g) {
        const float* bkr = bkp + g * 16 + qid * 2;
        bkf[g][0] = pack_h2(bkr[0], bkr[1]);
        bkf[g][1] = pack_h2(bkr[8], bkr[9]);
    }

    const long warp_base = (long)blockIdx.x * ROWS_PER_CTA + (long)wid * ROWS_PER_WARP;
    const char* zbytes = reinterpret_cast<const char*>(z) + warp_base * (ZD * 4);

    const uint32_t ring = smem_u32(zstage) + (uint32_t)wid * STAGE_BYTES;
    #define STAGE_ADDR(s) (ring + (uint32_t)(s) * (WARPS * STAGE_BYTES))

    #define ISSUE_STAGE(blk, s) do {                                          \
        const char* src = zbytes + (long)(blk) * STAGE_BYTES;                 \
        uint32_t dst = STAGE_ADDR(s);                                         \
        cp_async16(dst + lane * 16,        src + lane * 16);                  \
        cp_async16(dst + 512 + lane * 16,  src + 512 + lane * 16);            \
        cp_async16(dst + 1024 + lane * 16, src + 1024 + lane * 16);           \
        cp_async16(dst + 1536 + lane * 16, src + 1536 + lane * 16);           \
    } while (0)

    // prologue: stages 0..2
    ISSUE_STAGE(0, 0); CP_COMMIT();
    ISSUE_STAGE(1, 1); CP_COMMIT();
    ISSUE_STAGE(2, 2); CP_COMMIT();

    const uint32_t fo = (uint32_t)quad * 64 + (uint32_t)qid * 8;

    #pragma unroll 1
    for (int blk = 0; blk < TPW; ++blk) {
        CP_WAIT2();   // group 'blk' complete

        const uint32_t sb = STAGE_ADDR(blk % STAGES);
        float2 pA0 = lds64(sb + fo);                // (quad,    k qid*2)
        float2 pA1 = lds64(sb + fo + 8 * 64);       // (quad+8,  k qid*2)
        float2 pA2 = lds64(sb + fo + 32);           // (quad,    k qid*2+8)
        float2 pA3 = lds64(sb + fo + 8 * 64 + 32);
        float2 pB0 = lds64(sb + fo + 16 * 64);
        float2 pB1 = lds64(sb + fo + 24 * 64);
        float2 pB2 = lds64(sb + fo + 16 * 64 + 32);
        float2 pB3 = lds64(sb + fo + 24 * 64 + 32);

        uint32_t aA[4], aB[4];
        aA[0] = pack_h2(pA0.x, pA0.y);
        aA[1] = pack_h2(pA1.x, pA1.y);
        aA[2] = pack_h2(pA2.x, pA2.y);
        aA[3] = pack_h2(pA3.x, pA3.y);
        aB[0] = pack_h2(pB0.x, pB0.y);
        aB[1] = pack_h2(pB1.x, pB1.y);
        aB[2] = pack_h2(pB2.x, pB2.y);
        aB[3] = pack_h2(pB3.x, pB3.y);

        // refill stage blk+3 (slot just consumed; its LDS reads are complete
        // ~30 cyc after issue while cp.async data lands >200 cyc later)
        if (blk + 3 < TPW) {
            ISSUE_STAGE(blk + 3, (blk + 3) % STAGES);
        }
        CP_COMMIT();

        // ---- MMA1 + tanh: produce MMA2 A-fragments (16 regs) ----
        // group g, frag pos: [0]=(row q, k-lo) j=2g d01, [1]=(row q+8, k-lo) j=2g d23,
        //                    [2]=(row q, k-hi) j=2g+1 d01, [3]=(row q+8, k-hi) j=2g+1 d23
        uint32_t tA[16], tB[16];
        #pragma unroll
        for (int j = 0; j < 8; ++j) {
            float2 qd = sdk[j * 4 + qid];   // {dk0, dk1}, LDS.64 broadcast
            float dA[4], dB[4];
            mma_h_init(dA, aA, bh[j][0], bh[j][1], qd.x, qd.y);  // z*c + dk
            mma_h_init(dB, aB, bh[j][0], bh[j][1], qd.x, qd.y);
            const int base = (j >> 1) * 4 + (j & 1) * 2;
            tA[base]     = tanh2(pack_h2(dA[0], dA[1]));
            tA[base + 1] = tanh2(pack_h2(dA[2], dA[3]));
            tB[base]     = tanh2(pack_h2(dB[0], dB[1]));
            tB[base + 1] = tanh2(pack_h2(dB[2], dB[3]));
        }

        // ---- MMA2: y = a0 + tanh_vals @ bk  (fp32 accum, a0 folded in) ----
        float cA[4], cB[4];
        mma_h_init(cA, tA, bkf[0][0], bkf[0][1], a0, a0);
        mma_h_init(cB, tB, bkf[0][0], bkf[0][1], a0, a0);
        #pragma unroll
        for (int g = 1; g < 4; ++g) {
            mma_h_acc(cA, tA + g * 4, bkf[g][0], bkf[g][1]);
            mma_h_acc(cB, tB + g * 4, bkf[g][0], bkf[g][1]);
        }
        // every lane holds full sums: cA[0]=row quad, cA[2]=row quad+8,
        // cB[0]=row quad+16, cB[2]=row quad+24 (all N-columns identical)

        // coalesced store: lane (quad,qid) stores row quad + 8*qid
        float val = (qid == 0) ? cA[0] : (qid == 1) ? cA[2]
                  : (qid == 2) ? cB[0] : cB[2];
        out[warp_base + (long)blk * 32 + quad + 8 * qid] = val;
    }
    #undef ISSUE_STAGE
    #undef STAGE_ADDR
}

// ---- scalar tail (unused when B % 2048 == 0; B = 2M is) --------------------
__global__ void mave_tail(
    const float* __restrict__ z, const float* __restrict__ a0p,
    const float* __restrict__ bk, const float* __restrict__ ck,
    const float* __restrict__ dk, float* __restrict__ out,
    long start, long Btot)
{
    long row = start + (long)blockIdx.x * blockDim.x + threadIdx.x;
    if (row >= Btot) return;
    const float* zr = z + row * ZD;
    float zv[ZD];
    #pragma unroll
    for (int i = 0; i < ZD; ++i) zv[i] = zr[i];
    float acc = a0p[0];
    for (int k = 0; k < KN; ++k) {
        float h = dk[k];
        #pragma unroll
        for (int zi = 0; zi < ZD; ++zi) h = fmaf(ck[k * ZD + zi], zv[zi], h);
        acc = fmaf(bk[k], tanh_a(h), acc);
    }
    out[row] = acc;
}

extern "C" void kernel_launch(void* const* d_in, const int* in_sizes, int n_in,
                              void* d_out, int out_size) {
    const float* z  = (const float*)d_in[0];
    const float* a0 = (const float*)d_in[1];
    const float* bk = (const float*)d_in[2];
    const float* ck = (const float*)d_in[3];
    const float* dk = (const float*)d_in[4];
    float* out = (float*)d_out;

    static int smem_set = 0;
    if (!smem_set) {
        cudaFuncSetAttribute(mave_mma, cudaFuncAttributeMaxDynamicSharedMemorySize,
                             SMEM_DYN);
        smem_set = 1;
    }

    const long B = (long)in_sizes[0] / ZD;
    const long nfull = B / ROWS_PER_CTA;

    if (nfull > 0) {
        mave_mma<<<(int)nfull, NTHREADS, SMEM_DYN>>>(z, a0, bk, ck, dk, out);
    }
    const long rem = B - nfull * ROWS_PER_CTA;
    if (rem > 0) {
        mave_tail<<<(int)((rem + 255) / 256), 256>>>(z, a0, bk, ck, dk, out,
                                                     nfull * ROWS_PER_CTA, B);
    }
}

// round 16
// speedup vs baseline: 1.1016x; 1.1016x over previous
#include <cuda_runtime.h>
#include <cuda_fp16.h>
#include <cstdint>

#define ZD            16
#define KN            64
#define NTHREADS      256
#define WARPS         8
#define TPW           16                       // iterations per warp (16 rows each)
#define ROWS_PER_WARP (TPW * 16)               // 256
#define ROWS_PER_CTA  (WARPS * ROWS_PER_WARP)  // 2048

#define STAGES        4
#define STAGE_BYTES   1024                     // 16 rows x 64 B per warp
#define SMEM_DYN      (STAGES * WARPS * STAGE_BYTES)   // 32 KB

// ---- helpers ---------------------------------------------------------------
__device__ __forceinline__ uint32_t pack_h2(float lo, float hi) {
    uint32_t r;
    asm("cvt.rn.f16x2.f32 %0, %1, %2;" : "=r"(r) : "f"(hi), "f"(lo));
    return r;
}
__device__ __forceinline__ uint32_t tanh2(uint32_t h2) {
    uint32_t r;
    asm("tanh.approx.f16x2 %0, %1;" : "=r"(r) : "r"(h2));
    return r;
}
__device__ __forceinline__ float tanh_a(float x) {
    float r;
    asm("tanh.approx.f32 %0, %1;" : "=f"(r) : "f"(x));
    return r;
}
__device__ __forceinline__ uint32_t smem_u32(const void* p) {
    uint32_t a;
    asm("{ .reg .u64 t; cvta.to.shared.u64 t, %1; cvt.u32.u64 %0, t; }" : "=r"(a) : "l"(p));
    return a;
}
__device__ __forceinline__ void cp_async16(uint32_t dst, const void* src) {
    asm volatile("cp.async.cg.shared.global [%0], [%1], 16;" :: "r"(dst), "l"(src));
}
#define CP_COMMIT() asm volatile("cp.async.commit_group;" ::: "memory")
#define CP_WAIT2()  asm volatile("cp.async.wait_group 2;" ::: "memory")

__device__ __forceinline__ float2 lds64(uint32_t addr) {
    float2 v;
    asm volatile("ld.shared.v2.f32 {%0, %1}, [%2];" : "=f"(v.x), "=f"(v.y) : "r"(addr));
    return v;
}
// fp16 MMA, fp32 accum, C preloaded with {c0, c1, c0, c1}
__device__ __forceinline__ void mma_h_init(float* d, const uint32_t* a,
                                           uint32_t b0, uint32_t b1,
                                           float c0, float c1) {
    asm("mma.sync.aligned.m16n8k16.row.col.f32.f16.f16.f32 "
        "{%0,%1,%2,%3}, {%4,%5,%6,%7}, {%8,%9}, {%10,%11,%12,%13};"
        : "=f"(d[0]), "=f"(d[1]), "=f"(d[2]), "=f"(d[3])
        : "r"(a[0]), "r"(a[1]), "r"(a[2]), "r"(a[3]),
          "r"(b0), "r"(b1),
          "f"(c0), "f"(c1), "f"(c0), "f"(c1));
}
// fp16 MMA, fp32 accum in-place (C = D)
__device__ __forceinline__ void mma_h_acc(float* d, const uint32_t* a,
                                          uint32_t b0, uint32_t b1) {
    asm("mma.sync.aligned.m16n8k16.row.col.f32.f16.f16.f32 "
        "{%0,%1,%2,%3}, {%4,%5,%6,%7}, {%8,%9}, {%0,%1,%2,%3};"
        : "+f"(d[0]), "+f"(d[1]), "+f"(d[2]), "+f"(d[3])
        : "r"(a[0]), "r"(a[1]), "r"(a[2]), "r"(a[3]),
          "r"(b0), "r"(b1));
}

// ---- main kernel -----------------------------------------------------------
__global__ void __launch_bounds__(NTHREADS, 4) mave_mma(
    const float* __restrict__ z, const float* __restrict__ a0p,
    const float* __restrict__ bkp, const float* __restrict__ ck,
    const float* __restrict__ dkp, float* __restrict__ out)
{
    extern __shared__ char zstage[];          // [STAGES][WARPS][1024]
    __shared__ float2 sdk[KN / 2];            // {dk0, dk1} per column pair

    const int tid  = threadIdx.x;
    const int wid  = tid >> 5;
    const int lane = tid & 31;
    const int quad = lane >> 2;     // 0..7
    const int qid  = lane & 3;      // 0..3

    if (tid < KN / 2) {
        float2 v; v.x = dkp[2 * tid]; v.y = dkp[2 * tid + 1];
        sdk[tid] = v;
    }
    __syncthreads();
    const float a0 = a0p[0];

    // MMA1 B fragments: ck as plain fp16, 8 n-tiles, 16 regs
    uint32_t bh[8][2];
    #pragma unroll
    for (int j = 0; j < 8; ++j) {
        const float* cr = ck + (j * 8 + quad) * ZD + qid * 2;
        float2 g0 = *reinterpret_cast<const float2*>(cr);
        float2 g1 = *reinterpret_cast<const float2*>(cr + 8);
        bh[j][0] = pack_h2(g0.x, g0.y);
        bh[j][1] = pack_h2(g1.x, g1.y);
    }
    // MMA2 B fragments (bk over 64-node K dim in 4 slices of 16), 8 regs
    uint32_t bkf[4][2];
    #pragma unroll
    for (int g = 0; g < 4; ++g) {
        const float* bkr = bkp + g * 16 + qid * 2;
        bkf[g][0] = pack_h2(bkr[0], bkr[1]);
        bkf[g][1] = pack_h2(bkr[8], bkr[9]);
    }

    const long warp_base = (long)blockIdx.x * ROWS_PER_CTA + (long)wid * ROWS_PER_WARP;
    const char* zbytes = reinterpret_cast<const char*>(z) + warp_base * (ZD * 4);

    const uint32_t ring = smem_u32(zstage) + (uint32_t)wid * STAGE_BYTES;
    #define STAGE_ADDR(s) (ring + (uint32_t)(s) * (WARPS * STAGE_BYTES))

    // one stage = 16 rows x 64 B = 1024 B; 2 chunks of 16 B per lane
    #define ISSUE_STAGE(blk, s) do {                                          \
        const char* src = zbytes + (long)(blk) * STAGE_BYTES;                 \
        uint32_t dst = STAGE_ADDR(s);                                         \
        cp_async16(dst + lane * 16,       src + lane * 16);                   \
        cp_async16(dst + 512 + lane * 16, src + 512 + lane * 16);             \
    } while (0)

    // prologue: stages 0..2
    ISSUE_STAGE(0, 0); CP_COMMIT();
    ISSUE_STAGE(1, 1); CP_COMMIT();
    ISSUE_STAGE(2, 2); CP_COMMIT();

    const uint32_t fo = (uint32_t)quad * 64 + (uint32_t)qid * 8;

    #pragma unroll 1
    for (int blk = 0; blk < TPW; ++blk) {
        CP_WAIT2();   // group 'blk' complete

        const uint32_t sb = STAGE_ADDR(blk & (STAGES - 1));
        float2 p0 = lds64(sb + fo);                // (quad,    k qid*2)
        float2 p1 = lds64(sb + fo + 8 * 64);       // (quad+8,  k qid*2)
        float2 p2 = lds64(sb + fo + 32);           // (quad,    k qid*2+8)
        float2 p3 = lds64(sb + fo + 8 * 64 + 32);

        uint32_t aA[4];
        aA[0] = pack_h2(p0.x, p0.y);
        aA[1] = pack_h2(p1.x, p1.y);
        aA[2] = pack_h2(p2.x, p2.y);
        aA[3] = pack_h2(p3.x, p3.y);

        if (blk + 3 < TPW) {
            ISSUE_STAGE(blk + 3, (blk + 3) & (STAGES - 1));
        }
        CP_COMMIT();

        // fused MMA1 -> tanh -> MMA2-accumulate, 4 node-slices of 16
        float c[4];
        #pragma unroll
        for (int g = 0; g < 4; ++g) {
            uint32_t t[4];
            #pragma unroll
            for (int jj = 0; jj < 2; ++jj) {
                const int j = 2 * g + jj;
                float2 qd = sdk[j * 4 + qid];   // {dk0, dk1}, LDS.64 broadcast
                float d[4];
                mma_h_init(d, aA, bh[j][0], bh[j][1], qd.x, qd.y);  // z*c + dk
                t[jj * 2]     = tanh2(pack_h2(d[0], d[1]));
                t[jj * 2 + 1] = tanh2(pack_h2(d[2], d[3]));
            }
            if (g == 0) mma_h_init(c, t, bkf[0][0], bkf[0][1], a0, a0);
            else        mma_h_acc(c, t, bkf[g][0], bkf[g][1]);
        }
        // every lane: c[0] = y(row quad), c[2] = y(row quad+8)

        if (qid < 2) {
            float val = (qid == 0) ? c[0] : c[2];
            out[warp_base + (long)blk * 16 + quad + 8 * qid] = val;
        }
    }
    #undef ISSUE_STAGE
    #undef STAGE_ADDR
}

// ---- scalar tail (unused when B % 2048 == 0; B = 2M is) --------------------
__global__ void mave_tail(
    const float* __restrict__ z, const float* __restrict__ a0p,
    const float* __restrict__ bk, const float* __restrict__ ck,
    const float* __restrict__ dk, float* __restrict__ out,
    long start, long Btot)
{
    long row = start + (long)blockIdx.x * blockDim.x + threadIdx.x;
    if (row >= Btot) return;
    const float* zr = z + row * ZD;
    float zv[ZD];
    #pragma unroll
    for (int i = 0; i < ZD; ++i) zv[i] = zr[i];
    float acc = a0p[0];
    for (int k = 0; k < KN; ++k) {
        float h = dk[k];
        #pragma unroll
        for (int zi = 0; zi < ZD; ++zi) h = fmaf(ck[k * ZD + zi], zv[zi], h);
        acc = fmaf(bk[k], tanh_a(h), acc);
    }
    out[row] = acc;
}

extern "C" void kernel_launch(void* const* d_in, const int* in_sizes, int n_in,
                              void* d_out, int out_size) {
    const float* z  = (const float*)d_in[0];
    const float* a0 = (const float*)d_in[1];
    const float* bk = (const float*)d_in[2];
    const float* ck = (const float*)d_in[3];
    const float* dk = (const float*)d_in[4];
    float* out = (float*)d_out;

    static int smem_set = 0;
    if (!smem_set) {
        cudaFuncSetAttribute(mave_mma, cudaFuncAttributeMaxDynamicSharedMemorySize,
                             SMEM_DYN);
        smem_set = 1;
    }

    const long B = (long)in_sizes[0] / ZD;
    const long nfull = B / ROWS_PER_CTA;

    if (nfull > 0) {
        mave_mma<<<(int)nfull, NTHREADS, SMEM_DYN>>>(z, a0, bk, ck, dk, out);
    }
    const long rem = B - nfull * ROWS_PER_CTA;
    if (rem > 0) {
        mave_tail<<<(int)((rem + 255) / 256), 256>>>(z, a0, bk, ck, dk, out,
                                                     nfull * ROWS_PER_CTA, B);
    }
}

// round 17
// speedup vs baseline: 1.1025x; 1.0008x over previous
#include <cuda_runtime.h>
#include <cuda_fp16.h>
#include <cstdint>

#define ZD            16
#define KN            64
#define NTHREADS      256
#define WARPS         8
#define TPW           16                       // iterations per warp (16 rows each)
#define ROWS_PER_WARP (TPW * 16)               // 256
#define ROWS_PER_CTA  (WARPS * ROWS_PER_WARP)  // 2048

#define STAGES        4
#define STAGE_BYTES   1024                     // 16 rows x 64 B per warp
#define SMEM_DYN      (STAGES * WARPS * STAGE_BYTES)   // 32 KB

// ---- helpers ---------------------------------------------------------------
__device__ __forceinline__ uint32_t pack_h2(float lo, float hi) {
    uint32_t r;
    asm("cvt.rn.f16x2.f32 %0, %1, %2;" : "=r"(r) : "f"(hi), "f"(lo));
    return r;
}
__device__ __forceinline__ uint32_t tanh2(uint32_t h2) {
    uint32_t r;
    asm("tanh.approx.f16x2 %0, %1;" : "=r"(r) : "r"(h2));
    return r;
}
__device__ __forceinline__ float tanh_a(float x) {
    float r;
    asm("tanh.approx.f32 %0, %1;" : "=f"(r) : "f"(x));
    return r;
}
__device__ __forceinline__ uint32_t smem_u32(const void* p) {
    uint32_t a;
    asm("{ .reg .u64 t; cvta.to.shared.u64 t, %1; cvt.u32.u64 %0, t; }" : "=r"(a) : "l"(p));
    return a;
}
__device__ __forceinline__ void cp_async16(uint32_t dst, const void* src) {
    asm volatile("cp.async.cg.shared.global [%0], [%1], 16;" :: "r"(dst), "l"(src));
}
#define CP_COMMIT() asm volatile("cp.async.commit_group;" ::: "memory")
#define CP_WAIT2()  asm volatile("cp.async.wait_group 2;" ::: "memory")

__device__ __forceinline__ float2 lds64(uint32_t addr) {
    float2 v;
    asm volatile("ld.shared.v2.f32 {%0, %1}, [%2];" : "=f"(v.x), "=f"(v.y) : "r"(addr));
    return v;
}
__device__ __forceinline__ uint32_t lds32(uint32_t addr) {
    uint32_t v;
    asm volatile("ld.shared.b32 %0, [%1];" : "=r"(v) : "r"(addr));
    return v;
}
// fp16 MMA with fp16 accumulator/output: D,C are 2 packed f16x2 regs.
// D row layout: d0 = {row quad: col 2qid, col 2qid+1}, d1 = rows quad+8.
__device__ __forceinline__ void mma_h16(uint32_t& d0, uint32_t& d1,
                                        const uint32_t* a,
                                        uint32_t b0, uint32_t b1,
                                        uint32_t c0, uint32_t c1) {
    asm("mma.sync.aligned.m16n8k16.row.col.f16.f16.f16.f16 "
        "{%0,%1}, {%2,%3,%4,%5}, {%6,%7}, {%8,%9};"
        : "=r"(d0), "=r"(d1)
        : "r"(a[0]), "r"(a[1]), "r"(a[2]), "r"(a[3]),
          "r"(b0), "r"(b1), "r"(c0), "r"(c1));
}
// fp16 in, fp32 accum, C preloaded with {c0, c1, c0, c1}
__device__ __forceinline__ void mma_h_init(float* d, const uint32_t* a,
                                           uint32_t b0, uint32_t b1,
                                           float c0, float c1) {
    asm("mma.sync.aligned.m16n8k16.row.col.f32.f16.f16.f32 "
        "{%0,%1,%2,%3}, {%4,%5,%6,%7}, {%8,%9}, {%10,%11,%12,%13};"
        : "=f"(d[0]), "=f"(d[1]), "=f"(d[2]), "=f"(d[3])
        : "r"(a[0]), "r"(a[1]), "r"(a[2]), "r"(a[3]),
          "r"(b0), "r"(b1),
          "f"(c0), "f"(c1), "f"(c0), "f"(c1));
}
// fp16 in, fp32 accum in-place (C = D)
__device__ __forceinline__ void mma_h_acc(float* d, const uint32_t* a,
                                          uint32_t b0, uint32_t b1) {
    asm("mma.sync.aligned.m16n8k16.row.col.f32.f16.f16.f32 "
        "{%0,%1,%2,%3}, {%4,%5,%6,%7}, {%8,%9}, {%0,%1,%2,%3};"
        : "+f"(d[0]), "+f"(d[1]), "+f"(d[2]), "+f"(d[3])
        : "r"(a[0]), "r"(a[1]), "r"(a[2]), "r"(a[3]),
          "r"(b0), "r"(b1));
}

// ---- main kernel -----------------------------------------------------------
__global__ void __launch_bounds__(NTHREADS, 4) mave_mma(
    const float* __restrict__ z, const float* __restrict__ a0p,
    const float* __restrict__ bkp, const float* __restrict__ ck,
    const float* __restrict__ dkp, float* __restrict__ out)
{
    extern __shared__ char zstage[];          // [STAGES][WARPS][1024]
    __shared__ uint32_t sdk2[KN / 2];         // packed h2 {dk0, dk1} per column pair

    const int tid  = threadIdx.x;
    const int wid  = tid >> 5;
    const int lane = tid & 31;
    const int quad = lane >> 2;     // 0..7
    const int qid  = lane & 3;      // 0..3

    if (tid < KN / 2) {
        sdk2[tid] = pack_h2(dkp[2 * tid], dkp[2 * tid + 1]);
    }
    __syncthreads();
    const float a0 = a0p[0];

    // MMA1 B fragments: ck as plain fp16, 8 n-tiles, 16 regs
    uint32_t bh[8][2];
    #pragma unroll
    for (int j = 0; j < 8; ++j) {
        const float* cr = ck + (j * 8 + quad) * ZD + qid * 2;
        float2 g0 = *reinterpret_cast<const float2*>(cr);
        float2 g1 = *reinterpret_cast<const float2*>(cr + 8);
        bh[j][0] = pack_h2(g0.x, g0.y);
        bh[j][1] = pack_h2(g1.x, g1.y);
    }
    // MMA2 B fragments (bk over 64-node K dim in 4 slices of 16), 8 regs
    uint32_t bkf[4][2];
    #pragma unroll
    for (int g = 0; g < 4; ++g) {
        const float* bkr = bkp + g * 16 + qid * 2;
        bkf[g][0] = pack_h2(bkr[0], bkr[1]);
        bkf[g][1] = pack_h2(bkr[8], bkr[9]);
    }

    const long warp_base = (long)blockIdx.x * ROWS_PER_CTA + (long)wid * ROWS_PER_WARP;
    const char* zbytes = reinterpret_cast<const char*>(z) + warp_base * (ZD * 4);

    const uint32_t ring = smem_u32(zstage) + (uint32_t)wid * STAGE_BYTES;
    #define STAGE_ADDR(s) (ring + (uint32_t)(s) * (WARPS * STAGE_BYTES))

    // one stage = 16 rows x 64 B = 1024 B; 2 chunks of 16 B per lane
    #define ISSUE_STAGE(blk, s) do {                                          \
        const char* src = zbytes + (long)(blk) * STAGE_BYTES;                 \
        uint32_t dst = STAGE_ADDR(s);                                         \
        cp_async16(dst + lane * 16,       src + lane * 16);                   \
        cp_async16(dst + 512 + lane * 16, src + 512 + lane * 16);             \
    } while (0)

    // prologue: stages 0..2
    ISSUE_STAGE(0, 0); CP_COMMIT();
    ISSUE_STAGE(1, 1); CP_COMMIT();
    ISSUE_STAGE(2, 2); CP_COMMIT();

    const uint32_t fo = (uint32_t)quad * 64 + (uint32_t)qid * 8;
    const uint32_t sdk2_base = smem_u32(sdk2) + (uint32_t)qid * 4;

    #pragma unroll 1
    for (int blk = 0; blk < TPW; ++blk) {
        CP_WAIT2();   // group 'blk' complete

        const uint32_t sb = STAGE_ADDR(blk & (STAGES - 1));
        float2 p0 = lds64(sb + fo);                // (quad,    k qid*2)
        float2 p1 = lds64(sb + fo + 8 * 64);       // (quad+8,  k qid*2)
        float2 p2 = lds64(sb + fo + 32);           // (quad,    k qid*2+8)
        float2 p3 = lds64(sb + fo + 8 * 64 + 32);

        uint32_t aA[4];
        aA[0] = pack_h2(p0.x, p0.y);
        aA[1] = pack_h2(p1.x, p1.y);
        aA[2] = pack_h2(p2.x, p2.y);
        aA[3] = pack_h2(p3.x, p3.y);

        if (blk + 3 < TPW) {
            ISSUE_STAGE(blk + 3, (blk + 3) & (STAGES - 1));
        }
        CP_COMMIT();

        // fused MMA1(f16 out) -> tanh2 -> MMA2-accumulate, 4 node-slices of 16
        float c[4];
        #pragma unroll
        for (int g = 0; g < 4; ++g) {
            uint32_t t[4];
            #pragma unroll
            for (int jj = 0; jj < 2; ++jj) {
                const int j = 2 * g + jj;
                uint32_t qd = lds32(sdk2_base + (uint32_t)(j * 16));  // {dk0,dk1} h2
                uint32_t d0, d1;
                mma_h16(d0, d1, aA, bh[j][0], bh[j][1], qd, qd);  // z*c + dk, f16 out
                t[jj * 2]     = tanh2(d0);
                t[jj * 2 + 1] = tanh2(d1);
            }
            if (g == 0) mma_h_init(c, t, bkf[0][0], bkf[0][1], a0, a0);
            else        mma_h_acc(c, t, bkf[g][0], bkf[g][1]);
        }
        // every lane: c[0] = y(row quad), c[2] = y(row quad+8)

        if (qid < 2) {
            float val = (qid == 0) ? c[0] : c[2];
            out[warp_base + (long)blk * 16 + quad + 8 * qid] = val;
        }
    }
    #undef ISSUE_STAGE
    #undef STAGE_ADDR
}

// ---- scalar tail (unused when B % 2048 == 0; B = 2M is) --------------------
__global__ void mave_tail(
    const float* __restrict__ z, const float* __restrict__ a0p,
    const float* __restrict__ bk, const float* __restrict__ ck,
    const float* __restrict__ dk, float* __restrict__ out,
    long start, long Btot)
{
    long row = start + (long)blockIdx.x * blockDim.x + threadIdx.x;
    if (row >= Btot) return;
    const float* zr = z + row * ZD;
    float zv[ZD];
    #pragma unroll
    for (int i = 0; i < ZD; ++i) zv[i] = zr[i];
    float acc = a0p[0];
    for (int k = 0; k < KN; ++k) {
        float h = dk[k];
        #pragma unroll
        for (int zi = 0; zi < ZD; ++zi) h = fmaf(ck[k * ZD + zi], zv[zi], h);
        acc = fmaf(bk[k], tanh_a(h), acc);
    }
    out[row] = acc;
}

extern "C" void kernel_launch(void* const* d_in, const int* in_sizes, int n_in,
                              void* d_out, int out_size) {
    const float* z  = (const float*)d_in[0];
    const float* a0 = (const float*)d_in[1];
    const float* bk = (const float*)d_in[2];
    const float* ck = (const float*)d_in[3];
    const float* dk = (const float*)d_in[4];
    float* out = (float*)d_out;

    static int smem_set = 0;
    if (!smem_set) {
        cudaFuncSetAttribute(mave_mma, cudaFuncAttributeMaxDynamicSharedMemorySize,
                             SMEM_DYN);
        smem_set = 1;
    }

    const long B = (long)in_sizes[0] / ZD;
    const long nfull = B / ROWS_PER_CTA;

    if (nfull > 0) {
        mave_mma<<<(int)nfull, NTHREADS, SMEM_DYN>>>(z, a0, bk, ck, dk, out);
    }
    const long rem = B - nfull * ROWS_PER_CTA;
    if (rem > 0) {
        mave_tail<<<(int)((rem + 255) / 256), 256>>>(z, a0, bk, ck, dk, out,
                                                     nfull * ROWS_PER_CTA, B);
    }
}